// round 3
// baseline (speedup 1.0000x reference)
#include <cuda_runtime.h>
#include <math.h>

// Shapes (fixed): N=64, T=300, V=25, C=64, K=3, F=64, I=16, d=T*I=4800
#define SCALE_D 0.014433756729740645f   // 1/sqrt(4800)

// Scratch (module-static device memory; no runtime allocation)
__device__ float g_Spart[30 * 3 * 64 * 625];   // [chunk][k][n][v*25+w] partial scores, 14.4MB
__device__ float g_Aad[3 * 64 * 625];          // A_adapt [k][n][v*25+w]

// ---------------------------------------------------------------------------
// Kernel 1: attention score partials.
// Grid (30 t-chunks, 64 n), 256 threads. Each block accumulates, over its 10
// t-values, S[k][v][w] += (XWq_k + bq)(XWk_k + bk)^T in registers, then writes
// its chunk's partial to g_Spart (full coverage, no atomics -> deterministic).
// ---------------------------------------------------------------------------
__global__ __launch_bounds__(256) void score_kernel(
    const float* __restrict__ x,
    const float* __restrict__ Wq, const float* __restrict__ bq,
    const float* __restrict__ Wk, const float* __restrict__ bk)
{
    extern __shared__ float sm[];
    float* Gs  = sm;            // [64][96] combined Wq|Wk, cols j<48 Q (k*16+i), j>=48 K
    float* bs  = Gs + 6144;     // [96] bq|bk
    float* Xs  = bs + 96;       // [2][25][64]
    float* Qs  = Xs + 3200;     // [2][25][48]  Q with bias
    float* Kts = Qs + 2400;     // [2][3][16][28] K transposed (i-major, w contiguous)

    const int tid = threadIdx.x;
    const int chunk = blockIdx.x;
    const int n = blockIdx.y;

    // Load combined embedding weights into smem
    for (int e = tid; e < 6144; e += 256) {
        int c = e / 96, j = e % 96;
        float v;
        if (j < 48)  v = Wq[(j >> 4) * 1024 + c * 16 + (j & 15)];
        else { int jj = j - 48; v = Wk[(jj >> 4) * 1024 + c * 16 + (jj & 15)]; }
        Gs[e] = v;
    }
    if (tid < 96) bs[tid] = (tid < 48) ? bq[tid] : bk[tid - 48];

    // Persistent score accumulators: up to 2 tasks per thread (273 tasks total)
    float acc[2][2][4];
#pragma unroll
    for (int a = 0; a < 2; a++)
#pragma unroll
        for (int b2 = 0; b2 < 2; b2++)
#pragma unroll
            for (int c2 = 0; c2 < 4; c2++) acc[a][b2][c2] = 0.f;

    const float* xn = x + (n * 300 + chunk * 10) * 1600;

    for (int step = 0; step < 5; ++step) {
        __syncthreads();
        {   // load 2 consecutive t tiles (contiguous 3200 floats)
            const float4* src = (const float4*)(xn + step * 3200);
            float4* dst = (float4*)Xs;
            for (int e = tid; e < 800; e += 256) dst[e] = src[e];
        }
        __syncthreads();

        // --- Q/K embedding GEMM: E = X * [Wq|Wk] + bias, 240 tasks ---
        if (tid < 240) {
            int t2 = tid / 120, r = tid % 120;
            int qk = r / 60,   r2 = r % 60;
            int rowg = r2 / 12, ic = r2 % 12;
            int kq = ic >> 2,  i4 = ic & 3;

            float a0[5], a1[5], a2[5], a3[5];
#pragma unroll
            for (int rr = 0; rr < 5; rr++) { a0[rr] = a1[rr] = a2[rr] = a3[rr] = 0.f; }

            const float* Xb = Xs + t2 * 1600 + rowg * 320;
            const float4* G4 = (const float4*)Gs;
            const int gcol = qk * 12 + kq * 4 + i4;
#pragma unroll 8
            for (int c = 0; c < 64; ++c) {
                float4 g = G4[c * 24 + gcol];
#pragma unroll
                for (int rr = 0; rr < 5; ++rr) {
                    float xv = Xb[rr * 64 + c];
                    a0[rr] += xv * g.x; a1[rr] += xv * g.y;
                    a2[rr] += xv * g.z; a3[rr] += xv * g.w;
                }
            }
            const int bb0 = qk * 48 + kq * 16 + i4 * 4;
            const float b0 = bs[bb0], b1 = bs[bb0 + 1], b2 = bs[bb0 + 2], b3 = bs[bb0 + 3];
            if (qk == 0) {
#pragma unroll
                for (int rr = 0; rr < 5; ++rr) {
                    int row = rowg * 5 + rr;
                    float4 o = make_float4(a0[rr] + b0, a1[rr] + b1, a2[rr] + b2, a3[rr] + b3);
                    *(float4*)(Qs + t2 * 1200 + row * 48 + kq * 16 + i4 * 4) = o;
                }
            } else {
#pragma unroll
                for (int rr = 0; rr < 5; ++rr) {
                    int row = rowg * 5 + rr;
                    float* kb = Kts + t2 * 1344 + kq * 448 + (i4 * 4) * 28 + row;
                    kb[0]  = a0[rr] + b0;
                    kb[28] = a1[rr] + b1;
                    kb[56] = a2[rr] + b2;
                    kb[84] = a3[rr] + b3;
                }
            }
        }
        __syncthreads();

        // --- Score accumulation: S[k][v][w] += Q.K^T over i=16, for 2 t's ---
#pragma unroll
        for (int ti = 0; ti < 2; ++ti) {
#pragma unroll
            for (int task = 0; task < 2; ++task) {
                int s = tid + task * 256;
                if (s < 273) {
                    int kq = s / 91, r = s % 91;
                    int w4 = r / 13, vp = r % 13;
                    int v0 = 2 * vp;
                    int v1 = (2 * vp + 1 < 25) ? (2 * vp + 1) : 24;  // clamped; discarded at store
                    const float* q0p = Qs + ti * 1200 + v0 * 48 + kq * 16;
                    const float* q1p = Qs + ti * 1200 + v1 * 48 + kq * 16;
                    const float4* kt = (const float4*)(Kts + ti * 1344 + kq * 448 + w4 * 4);
#pragma unroll
                    for (int i = 0; i < 16; ++i) {
                        float4 kv = kt[i * 7];
                        float q0 = q0p[i], q1 = q1p[i];
                        acc[task][0][0] += q0 * kv.x; acc[task][0][1] += q0 * kv.y;
                        acc[task][0][2] += q0 * kv.z; acc[task][0][3] += q0 * kv.w;
                        acc[task][1][0] += q1 * kv.x; acc[task][1][1] += q1 * kv.y;
                        acc[task][1][2] += q1 * kv.z; acc[task][1][3] += q1 * kv.w;
                    }
                }
            }
        }
    }

    // --- write chunk partials ---
#pragma unroll
    for (int task = 0; task < 2; ++task) {
        int s = tid + task * 256;
        if (s < 273) {
            int kq = s / 91, r = s % 91;
            int w4 = r / 13, vp = r % 13;
            float* base = g_Spart + ((chunk * 3 + kq) * 64 + n) * 625;
#pragma unroll
            for (int vv = 0; vv < 2; ++vv) {
                int v = 2 * vp + vv;
                if (v < 25) {
#pragma unroll
                    for (int j = 0; j < 4; ++j) {
                        int w = w4 * 4 + j;
                        if (w < 25) base[v * 25 + w] = acc[task][vv][j];
                    }
                }
            }
        }
    }
}

// ---------------------------------------------------------------------------
// Kernel 2: reduce chunk partials (deterministic order), softmax over w, add A.
// Grid 192 = (k*64+n), 128 threads.
// ---------------------------------------------------------------------------
__global__ __launch_bounds__(128) void softmax_kernel(const float* __restrict__ A)
{
    __shared__ float S[625];
    const int b = blockIdx.x;
    const int kq = b / 64, n = b % 64;
    const int tid = threadIdx.x;

    for (int e = tid; e < 625; e += 128) {
        float s = 0.f;
        int base = ((kq * 64) + n) * 625 + e;
#pragma unroll 6
        for (int ch = 0; ch < 30; ++ch) s += g_Spart[ch * 120000 + base];
        S[e] = s;
    }
    __syncthreads();

    if (tid < 25) {
        const int v = tid;
        float m = -1e30f;
#pragma unroll
        for (int w = 0; w < 25; ++w) {
            float z = S[v * 25 + w] * SCALE_D;
            m = fmaxf(m, z);
        }
        float p[25];
        float sum = 0.f;
#pragma unroll
        for (int w = 0; w < 25; ++w) {
            p[w] = expf(S[v * 25 + w] * SCALE_D - m);
            sum += p[w];
        }
        float inv = 1.f / sum;
        float* dst = g_Aad + ((kq * 64) + n) * 625 + v * 25;
        const float* Ab = A + kq * 625 + v * 25;
#pragma unroll
        for (int w = 0; w < 25; ++w) dst[w] = Ab[w] + p[w] * inv;
    }
}

// ---------------------------------------------------------------------------
// Kernel 3: main path. Grid (25 t-chunks of 12, 64 n), 256 threads.
// Per t: H = X*W (25x192) in smem, then Y[w][f] = ybias + sum_{k,v} A[k][v][w]*H[v][k*64+f].
// Bias of the 1x1 conv folded into ybias = sum_k b_k (x) colsum_k(A_adapt).
// ---------------------------------------------------------------------------
__global__ __launch_bounds__(256) void main_kernel(
    const float* __restrict__ x, const float* __restrict__ W,
    const float* __restrict__ b, float* __restrict__ y)
{
    extern __shared__ float sm[];
    float* Ws    = sm;             // [64][192] = 12288
    float* Xs    = Ws + 12288;     // [25][64]  = 1600
    float* Hs    = Xs + 1600;      // [25][192] = 4800
    float* ybias = Hs + 4800;      // [25][64]  = 1600
    float* As    = ybias + 1600;   // [3][25][25] = 1875
    float* csum  = As + 1875;      // [3][25] = 75

    const int tid = threadIdx.x;
    const int n = blockIdx.y;
    const int tc = blockIdx.x;

    {   // load W (contiguous) and A_adapt for this n
        const float4* src = (const float4*)W;
        float4* dst = (float4*)Ws;
        for (int e = tid; e < 3072; e += 256) dst[e] = src[e];
    }
    for (int e = tid; e < 1875; e += 256) {
        int k = e / 625, rem = e % 625;
        As[e] = g_Aad[(k * 64 + n) * 625 + rem];
    }
    __syncthreads();

    if (tid < 75) {
        int k = tid / 25, w = tid % 25;
        float s = 0.f;
#pragma unroll
        for (int v = 0; v < 25; ++v) s += As[k * 625 + v * 25 + w];
        csum[tid] = s;
    }
    __syncthreads();
    for (int e = tid; e < 1600; e += 256) {
        int w = e / 64, f = e % 64;
        ybias[e] = b[f] * csum[w] + b[64 + f] * csum[25 + w] + b[128 + f] * csum[50 + w];
    }

    const int col4 = tid % 48;      // H phase (tid < 240)
    const int rowg = tid / 48;
    const int f4 = tid % 16;        // Y phase
    const int wg = tid / 16;
    const int w0 = wg;
    const int w1v = wg + 16;
    const int w1 = (w1v < 25) ? w1v : 0;   // clamped; store guarded

    for (int tt = 0; tt < 12; ++tt) {
        const int t = tc * 12 + tt;
        __syncthreads();
        {   // load X tile (contiguous 1600 floats)
            const float4* src = (const float4*)(x + (n * 300 + t) * 1600);
            float4* dst = (float4*)Xs;
            for (int e = tid; e < 400; e += 256) dst[e] = src[e];
        }
        __syncthreads();

        // --- H = X * W : 25x192, 5 rows x float4 per thread ---
        if (tid < 240) {
            float a0[5], a1[5], a2[5], a3[5];
#pragma unroll
            for (int r = 0; r < 5; ++r) { a0[r] = a1[r] = a2[r] = a3[r] = 0.f; }
            const float* Xb = Xs + rowg * 320;
            const float4* W4 = (const float4*)Ws;
#pragma unroll 8
            for (int c = 0; c < 64; ++c) {
                float4 wv = W4[c * 48 + col4];
#pragma unroll
                for (int r = 0; r < 5; ++r) {
                    float xv = Xb[r * 64 + c];
                    a0[r] += xv * wv.x; a1[r] += xv * wv.y;
                    a2[r] += xv * wv.z; a3[r] += xv * wv.w;
                }
            }
            float4* H4 = (float4*)Hs;
#pragma unroll
            for (int r = 0; r < 5; ++r)
                H4[(rowg * 5 + r) * 48 + col4] = make_float4(a0[r], a1[r], a2[r], a3[r]);
        }
        __syncthreads();

        // --- Y[w][f] = ybias + sum_k sum_v A[k][v][w] * H[v][k*64+f] ---
        {
            const float4* H4 = (const float4*)Hs;
            const float4* yb4 = (const float4*)ybias;
            float4 s0 = yb4[w0 * 16 + f4];
            float4 s1 = yb4[w1 * 16 + f4];
#pragma unroll
            for (int k = 0; k < 3; ++k) {
                const float* Ab = As + k * 625;
                const int hcol = k * 16 + f4;
#pragma unroll
                for (int v = 0; v < 25; ++v) {
                    float4 h = H4[v * 48 + hcol];
                    float av0 = Ab[v * 25 + w0];
                    float av1 = Ab[v * 25 + w1];
                    s0.x += av0 * h.x; s0.y += av0 * h.y; s0.z += av0 * h.z; s0.w += av0 * h.w;
                    s1.x += av1 * h.x; s1.y += av1 * h.y; s1.z += av1 * h.z; s1.w += av1 * h.w;
                }
            }
            float4* yout = (float4*)(y + (n * 300 + t) * 1600);
            yout[w0 * 16 + f4] = s0;
            if (w1v < 25) yout[w1v * 16 + f4] = s1;
        }
    }
}

// ---------------------------------------------------------------------------
extern "C" void kernel_launch(void* const* d_in, const int* in_sizes, int n_in,
                              void* d_out, int out_size)
{
    const float* x  = (const float*)d_in[0];
    const float* A  = (const float*)d_in[1];
    const float* W  = (const float*)d_in[2];
    const float* b  = (const float*)d_in[3];
    const float* Wq = (const float*)d_in[4];
    const float* bq = (const float*)d_in[5];
    const float* Wk = (const float*)d_in[6];
    const float* bk = (const float*)d_in[7];
    float* y = (float*)d_out;

    const int score_smem = 14528 * 4;   // 58112 B
    const int main_smem  = 22238 * 4;   // 88952 B
    cudaFuncSetAttribute(score_kernel, cudaFuncAttributeMaxDynamicSharedMemorySize, score_smem);
    cudaFuncSetAttribute(main_kernel,  cudaFuncAttributeMaxDynamicSharedMemorySize, main_smem);

    score_kernel<<<dim3(30, 64), 256, score_smem>>>(x, Wq, bq, Wk, bk);
    softmax_kernel<<<192, 128>>>(A);
    main_kernel<<<dim3(25, 64), 256, main_smem>>>(x, W, b, y);
}

// round 4
// speedup vs baseline: 1.2941x; 1.2941x over previous
#include <cuda_runtime.h>
#include <math.h>

// Shapes (fixed): N=64, T=300, V=25, C=64, K=3, F=64, I=16, d=T*I=4800
#define SCALE_D 0.014433756729740645f   // 1/sqrt(4800)

// Scratch (module-static device memory; no runtime allocation)
__device__ float g_Spart[30 * 3 * 64 * 625];   // [chunk][k][n][v*25+w] partial scores
__device__ float g_Aad[3 * 64 * 625];          // A_adapt [k][n][v*25+w]

// ---------------------------------------------------------------------------
// Kernel 1: attention score partials.
// Grid (30 t-chunks, 64 n), 256 threads. Q and K both stored i-major with
// padded row stride 28 -> all score-phase smem loads are broadcast /
// bank-distinct. X tile padded to row stride 68 (bank-distinct across rowg).
// ---------------------------------------------------------------------------
__global__ __launch_bounds__(256) void score_kernel(
    const float* __restrict__ x,
    const float* __restrict__ Wq, const float* __restrict__ bq,
    const float* __restrict__ Wk, const float* __restrict__ bk)
{
    extern __shared__ float sm[];
    float* Gs = sm;            // [64][96] combined Wq|Wk (j<48 Q, j>=48 K)
    float* bs = Gs + 6144;     // [96]
    float* Xs = bs + 96;       // [2][25][68] padded = 3400
    float* Qt = Xs + 3400;     // [2][3][16][28] = 2688 (i-major, v contiguous)
    float* Kt = Qt + 2688;     // [2][3][16][28] = 2688
    // total 15016 floats = 60064 B

    const int tid = threadIdx.x;
    const int chunk = blockIdx.x;
    const int n = blockIdx.y;

    // Load combined embedding weights into smem
    for (int e = tid; e < 6144; e += 256) {
        int c = e / 96, j = e % 96;
        float v;
        if (j < 48)  v = Wq[(j >> 4) * 1024 + c * 16 + (j & 15)];
        else { int jj = j - 48; v = Wk[(jj >> 4) * 1024 + c * 16 + (jj & 15)]; }
        Gs[e] = v;
    }
    if (tid < 96) bs[tid] = (tid < 48) ? bq[tid] : bk[tid - 48];

    // Persistent score accumulators: up to 2 tasks per thread (273 tasks)
    float acc[2][2][4];
#pragma unroll
    for (int a = 0; a < 2; a++)
#pragma unroll
        for (int b2 = 0; b2 < 2; b2++)
#pragma unroll
            for (int c2 = 0; c2 < 4; c2++) acc[a][b2][c2] = 0.f;

    const float* xn = x + (n * 300 + chunk * 10) * 1600;

    // Task decode (score phase), hoisted
    int s0 = tid, s1 = tid + 256;
    int kq0 = s0 / 91, r0 = s0 % 91, w40 = r0 / 13, vp0 = r0 % 13;
    int kq1 = s1 / 91, r1 = s1 % 91, w41 = r1 / 13, vp1 = r1 % 13;

    for (int step = 0; step < 5; ++step) {
        __syncthreads();
        {   // load 2 consecutive t tiles (800 float4), remap rows to stride 68
            const float4* src = (const float4*)(xn + step * 3200);
            float4* dst = (float4*)Xs;
            for (int e = tid; e < 800; e += 256) {
                int tile = e / 400, er = e % 400;
                int row = er >> 4, col = er & 15;
                dst[tile * 425 + row * 17 + col] = src[e];
            }
        }
        __syncthreads();

        // --- Q/K embedding GEMM: E = X * [Wq|Wk] + bias, 240 tasks ---
        if (tid < 240) {
            int t2 = tid / 120, r = tid % 120;
            int qk = r / 60,   r2 = r % 60;
            int rowg = r2 / 12, ic = r2 % 12;
            int kq = ic >> 2,  i4 = ic & 3;

            float a0[5], a1[5], a2[5], a3[5];
#pragma unroll
            for (int rr = 0; rr < 5; rr++) { a0[rr] = a1[rr] = a2[rr] = a3[rr] = 0.f; }

            const float* Xb = Xs + t2 * 1700 + rowg * 340;
            const float4* G4 = (const float4*)Gs;
            const int gcol = qk * 12 + kq * 4 + i4;
#pragma unroll 8
            for (int c = 0; c < 64; ++c) {
                float4 g = G4[c * 24 + gcol];
#pragma unroll
                for (int rr = 0; rr < 5; ++rr) {
                    float xv = Xb[rr * 68 + c];
                    a0[rr] += xv * g.x; a1[rr] += xv * g.y;
                    a2[rr] += xv * g.z; a3[rr] += xv * g.w;
                }
            }
            const int bb0 = qk * 48 + kq * 16 + i4 * 4;
            const float b0 = bs[bb0], b1 = bs[bb0 + 1], b2 = bs[bb0 + 2], b3 = bs[bb0 + 3];
            // transposed store: E[i][v], row stride 28
            float* eb = (qk ? Kt : Qt) + t2 * 1344 + kq * 448 + (i4 * 4) * 28;
#pragma unroll
            for (int rr = 0; rr < 5; ++rr) {
                int row = rowg * 5 + rr;
                eb[row]      = a0[rr] + b0;
                eb[28 + row] = a1[rr] + b1;
                eb[56 + row] = a2[rr] + b2;
                eb[84 + row] = a3[rr] + b3;
            }
        }
        __syncthreads();

        // --- Score accumulation: S[k][v][w] += Q^T.K over i=16, for 2 t's ---
#pragma unroll
        for (int ti = 0; ti < 2; ++ti) {
            // task 0 (always active: tid < 273)
            {
                int v0 = 2 * vp0;
                int v1 = (2 * vp0 + 1 < 25) ? (2 * vp0 + 1) : 24;
                const float* qb = Qt + ti * 1344 + kq0 * 448;
                const float4* kt = (const float4*)(Kt + ti * 1344 + kq0 * 448 + w40 * 4);
#pragma unroll
                for (int i = 0; i < 16; ++i) {
                    float4 kv = kt[i * 7];
                    float q0 = qb[i * 28 + v0], q1 = qb[i * 28 + v1];
                    acc[0][0][0] += q0 * kv.x; acc[0][0][1] += q0 * kv.y;
                    acc[0][0][2] += q0 * kv.z; acc[0][0][3] += q0 * kv.w;
                    acc[0][1][0] += q1 * kv.x; acc[0][1][1] += q1 * kv.y;
                    acc[0][1][2] += q1 * kv.z; acc[0][1][3] += q1 * kv.w;
                }
            }
            if (s1 < 273) {
                int v0 = 2 * vp1;
                int v1 = (2 * vp1 + 1 < 25) ? (2 * vp1 + 1) : 24;
                const float* qb = Qt + ti * 1344 + kq1 * 448;
                const float4* kt = (const float4*)(Kt + ti * 1344 + kq1 * 448 + w41 * 4);
#pragma unroll
                for (int i = 0; i < 16; ++i) {
                    float4 kv = kt[i * 7];
                    float q0 = qb[i * 28 + v0], q1 = qb[i * 28 + v1];
                    acc[1][0][0] += q0 * kv.x; acc[1][0][1] += q0 * kv.y;
                    acc[1][0][2] += q0 * kv.z; acc[1][0][3] += q0 * kv.w;
                    acc[1][1][0] += q1 * kv.x; acc[1][1][1] += q1 * kv.y;
                    acc[1][1][2] += q1 * kv.z; acc[1][1][3] += q1 * kv.w;
                }
            }
        }
    }

    // --- write chunk partials ---
#pragma unroll
    for (int task = 0; task < 2; ++task) {
        int s = tid + task * 256;
        if (s < 273) {
            int kq = s / 91, r = s % 91;
            int w4 = r / 13, vp = r % 13;
            float* base = g_Spart + ((chunk * 3 + kq) * 64 + n) * 625;
#pragma unroll
            for (int vv = 0; vv < 2; ++vv) {
                int v = 2 * vp + vv;
                if (v < 25) {
#pragma unroll
                    for (int j = 0; j < 4; ++j) {
                        int w = w4 * 4 + j;
                        if (w < 25) base[v * 25 + w] = acc[task][vv][j];
                    }
                }
            }
        }
    }
}

// ---------------------------------------------------------------------------
// Kernel 2: reduce chunk partials (deterministic order), softmax, add A.
// ---------------------------------------------------------------------------
__global__ __launch_bounds__(128) void softmax_kernel(const float* __restrict__ A)
{
    __shared__ float S[625];
    const int b = blockIdx.x;
    const int kq = b / 64, n = b % 64;
    const int tid = threadIdx.x;

    for (int e = tid; e < 625; e += 128) {
        float s = 0.f;
        int base = ((kq * 64) + n) * 625 + e;
#pragma unroll 6
        for (int ch = 0; ch < 30; ++ch) s += g_Spart[ch * 120000 + base];
        S[e] = s;
    }
    __syncthreads();

    if (tid < 25) {
        const int v = tid;
        float m = -1e30f;
#pragma unroll
        for (int w = 0; w < 25; ++w) {
            float z = S[v * 25 + w] * SCALE_D;
            m = fmaxf(m, z);
        }
        float p[25];
        float sum = 0.f;
#pragma unroll
        for (int w = 0; w < 25; ++w) {
            p[w] = expf(S[v * 25 + w] * SCALE_D - m);
            sum += p[w];
        }
        float inv = 1.f / sum;
        float* dst = g_Aad + ((kq * 64) + n) * 625 + v * 25;
        const float* Ab = A + kq * 625 + v * 25;
#pragma unroll
        for (int w = 0; w < 25; ++w) dst[w] = Ab[w] + p[w] * inv;
    }
}

// ---------------------------------------------------------------------------
// Kernel 3: main path. Grid (25 t-chunks of 12, 64 n), 256 threads.
// H = X*W in smem (5r x float4 tiles), then Y retiled 4w x 4f (2 B/FMA).
// ---------------------------------------------------------------------------
__global__ __launch_bounds__(256) void main_kernel(
    const float* __restrict__ x, const float* __restrict__ W,
    const float* __restrict__ b, float* __restrict__ y)
{
    extern __shared__ float sm[];
    float* Ws    = sm;             // [64][192] = 12288
    float* Xs    = Ws + 12288;     // [25][68] padded = 1700
    float* Hs    = Xs + 1700;      // [25][192] = 4800
    float* ybias = Hs + 4800;      // [25][64]  = 1600
    float* As    = ybias + 1600;   // [3][25][25] + pad = 1880
    float* csum  = As + 1880;      // [3][25]+pad = 77
    // total 22345 floats = 89380 B

    const int tid = threadIdx.x;
    const int n = blockIdx.y;
    const int tc = blockIdx.x;

    {   // load W (contiguous) and A_adapt for this n
        const float4* src = (const float4*)W;
        float4* dst = (float4*)Ws;
        for (int e = tid; e < 3072; e += 256) dst[e] = src[e];
    }
    for (int e = tid; e < 1875; e += 256) {
        int k = e / 625, rem = e % 625;
        As[e] = g_Aad[(k * 64 + n) * 625 + rem];
    }
    if (tid < 5) As[1875 + tid] = 0.f;   // pad (OOB-safe reads for w4=6)
    __syncthreads();

    if (tid < 75) {
        int k = tid / 25, w = tid % 25;
        float s = 0.f;
#pragma unroll
        for (int v = 0; v < 25; ++v) s += As[k * 625 + v * 25 + w];
        csum[tid] = s;
    }
    __syncthreads();
    for (int e = tid; e < 1600; e += 256) {
        int w = e / 64, f = e % 64;
        ybias[e] = b[f] * csum[w] + b[64 + f] * csum[25 + w] + b[128 + f] * csum[50 + w];
    }

    const int col4 = tid % 48;      // H phase (tid < 240)
    const int rowg = tid / 48;
    const int w4 = tid / 16;        // Y phase (tid < 112): w-group 0..6
    const int f4 = tid % 16;        // f-group 0..15

    for (int tt = 0; tt < 12; ++tt) {
        const int t = tc * 12 + tt;
        __syncthreads();
        {   // load X tile (400 float4), remap rows to stride 68
            const float4* src = (const float4*)(x + (n * 300 + t) * 1600);
            float4* dst = (float4*)Xs;
            for (int e = tid; e < 400; e += 256) {
                int row = e >> 4, col = e & 15;
                dst[row * 17 + col] = src[e];
            }
        }
        __syncthreads();

        // --- H = X * W : 25x192, 5 rows x float4 per thread (240 threads) ---
        if (tid < 240) {
            float a0[5], a1[5], a2[5], a3[5];
#pragma unroll
            for (int r = 0; r < 5; ++r) { a0[r] = a1[r] = a2[r] = a3[r] = 0.f; }
            const float* Xb = Xs + rowg * 340;
            const float4* W4 = (const float4*)Ws;
#pragma unroll 8
            for (int c = 0; c < 64; ++c) {
                float4 wv = W4[c * 48 + col4];
#pragma unroll
                for (int r = 0; r < 5; ++r) {
                    float xv = Xb[r * 68 + c];
                    a0[r] += xv * wv.x; a1[r] += xv * wv.y;
                    a2[r] += xv * wv.z; a3[r] += xv * wv.w;
                }
            }
            float4* H4 = (float4*)Hs;
#pragma unroll
            for (int r = 0; r < 5; ++r)
                H4[(rowg * 5 + r) * 48 + col4] = make_float4(a0[r], a1[r], a2[r], a3[r]);
        }
        __syncthreads();

        // --- Y: 4w x 4f tiles, 112 threads. 32B smem per 16 FMA. ---
        if (tid < 112) {
            const float4* H4 = (const float4*)Hs;
            const float4* yb4 = (const float4*)ybias;
            float4 s[4];
#pragma unroll
            for (int j = 0; j < 4; ++j) {
                int w = w4 * 4 + j;
                s[j] = (w < 25) ? yb4[w * 16 + f4] : make_float4(0.f, 0.f, 0.f, 0.f);
            }
#pragma unroll
            for (int k = 0; k < 3; ++k) {
                const float* Ab = As + k * 625 + w4 * 4;
                const int hcol = k * 16 + f4;
#pragma unroll
                for (int v = 0; v < 25; ++v) {
                    float4 h = H4[v * 48 + hcol];
                    float av0 = Ab[v * 25 + 0];
                    float av1 = Ab[v * 25 + 1];
                    float av2 = Ab[v * 25 + 2];
                    float av3 = Ab[v * 25 + 3];
                    s[0].x += av0 * h.x; s[0].y += av0 * h.y; s[0].z += av0 * h.z; s[0].w += av0 * h.w;
                    s[1].x += av1 * h.x; s[1].y += av1 * h.y; s[1].z += av1 * h.z; s[1].w += av1 * h.w;
                    s[2].x += av2 * h.x; s[2].y += av2 * h.y; s[2].z += av2 * h.z; s[2].w += av2 * h.w;
                    s[3].x += av3 * h.x; s[3].y += av3 * h.y; s[3].z += av3 * h.z; s[3].w += av3 * h.w;
                }
            }
            float4* yout = (float4*)(y + (n * 300 + t) * 1600);
#pragma unroll
            for (int j = 0; j < 4; ++j) {
                int w = w4 * 4 + j;
                if (w < 25) yout[w * 16 + f4] = s[j];
            }
        }
    }
}

// ---------------------------------------------------------------------------
extern "C" void kernel_launch(void* const* d_in, const int* in_sizes, int n_in,
                              void* d_out, int out_size)
{
    const float* x  = (const float*)d_in[0];
    const float* A  = (const float*)d_in[1];
    const float* W  = (const float*)d_in[2];
    const float* b  = (const float*)d_in[3];
    const float* Wq = (const float*)d_in[4];
    const float* bq = (const float*)d_in[5];
    const float* Wk = (const float*)d_in[6];
    const float* bk = (const float*)d_in[7];
    float* y = (float*)d_out;

    const int score_smem = 15016 * 4;   // 60064 B
    const int main_smem  = 22345 * 4;   // 89380 B
    cudaFuncSetAttribute(score_kernel, cudaFuncAttributeMaxDynamicSharedMemorySize, score_smem);
    cudaFuncSetAttribute(main_kernel,  cudaFuncAttributeMaxDynamicSharedMemorySize, main_smem);

    score_kernel<<<dim3(30, 64), 256, score_smem>>>(x, Wq, bq, Wk, bk);
    softmax_kernel<<<192, 128>>>(A);
    main_kernel<<<dim3(25, 64), 256, main_smem>>>(x, W, b, y);
}

// round 5
// speedup vs baseline: 1.2949x; 1.0006x over previous
#include <cuda_runtime.h>
#include <math.h>

// Shapes (fixed): N=64, T=300, V=25, C=64, K=3, F=64, I=16, d=T*I=4800
#define SCALE_D 0.014433756729740645f   // 1/sqrt(4800)

// Scratch (module-static device memory; no runtime allocation)
__device__ float g_Spart[30 * 3 * 64 * 625];   // [chunk][k][n][v*25+w] partial scores
__device__ float g_Aad[3 * 64 * 625];          // A_adapt [k][n][v*25+w]

// ---------------------------------------------------------------------------
// Kernel 1: attention score partials.
// Grid (30 t-chunks, 64 n), 256 threads.
// Embedding GEMM: c-loop by 4, float4 X loads (8.9 FMA/LDS).
// Score phase: 147 threads, 4v x 4w tiles, float4 Q + float4 K per i (8 FMA/LDS).
// ---------------------------------------------------------------------------
__global__ __launch_bounds__(256) void score_kernel(
    const float* __restrict__ x,
    const float* __restrict__ Wq, const float* __restrict__ bq,
    const float* __restrict__ Wk, const float* __restrict__ bk)
{
    extern __shared__ float sm[];
    float* Gs = sm;            // [64][96] combined Wq|Wk (j<48 Q, j>=48 K)
    float* bs = Gs + 6144;     // [96]
    float* Xs = bs + 96;       // [2][25][68] padded = 3400
    float* Qt = Xs + 3400;     // [2][3][16][28] = 2688 (i-major, v contiguous)
    float* Kt = Qt + 2688;     // [2][3][16][28] = 2688
    // total 15016 floats = 60064 B

    const int tid = threadIdx.x;
    const int chunk = blockIdx.x;
    const int n = blockIdx.y;

    // Load combined embedding weights into smem
    for (int e = tid; e < 6144; e += 256) {
        int c = e / 96, j = e % 96;
        float v;
        if (j < 48)  v = Wq[(j >> 4) * 1024 + c * 16 + (j & 15)];
        else { int jj = j - 48; v = Wk[(jj >> 4) * 1024 + c * 16 + (jj & 15)]; }
        Gs[e] = v;
    }
    if (tid < 96) bs[tid] = (tid < 48) ? bq[tid] : bk[tid - 48];

    // Score-phase task decode: 147 tasks = 3 kq x 7 w4 x 7 vp (4v x 4w tiles)
    const int kq_s = tid / 49;
    const int rs   = tid % 49;
    const int w4_s = rs / 7;
    const int vp_s = rs % 7;
    const bool score_active = (tid < 147);

    // Persistent score accumulators [vi][wj]
    float acc[4][4];
#pragma unroll
    for (int a = 0; a < 4; a++)
#pragma unroll
        for (int b2 = 0; b2 < 4; b2++) acc[a][b2] = 0.f;

    const float* xn = x + (n * 300 + chunk * 10) * 1600;

    // Embedding task decode (240 active)
    const int t2   = tid / 120;
    const int re   = tid % 120;
    const int qk   = re / 60;
    const int r2   = re % 60;
    const int rowg = r2 / 12;
    const int ic   = r2 % 12;
    const int kq_e = ic >> 2;
    const int i4   = ic & 3;
    const int gcol = qk * 12 + kq_e * 4 + i4;

    for (int step = 0; step < 5; ++step) {
        __syncthreads();
        {   // load 2 consecutive t tiles (800 float4), remap rows to stride 68
            const float4* src = (const float4*)(xn + step * 3200);
            float4* dst = (float4*)Xs;
            for (int e = tid; e < 800; e += 256) {
                int tile = e / 400, er = e % 400;
                int row = er >> 4, col = er & 15;
                dst[tile * 425 + row * 17 + col] = src[e];
            }
        }
        __syncthreads();

        // --- Q/K embedding GEMM: E = X * [Wq|Wk] + bias, 240 tasks ---
        if (tid < 240) {
            float a0[5], a1[5], a2[5], a3[5];
#pragma unroll
            for (int rr = 0; rr < 5; rr++) { a0[rr] = a1[rr] = a2[rr] = a3[rr] = 0.f; }

            const float* Xb = Xs + t2 * 1700 + rowg * 340;
            const float4* G4 = (const float4*)Gs;
#pragma unroll 4
            for (int c4 = 0; c4 < 16; ++c4) {
                float4 xr[5];
#pragma unroll
                for (int rr = 0; rr < 5; ++rr)
                    xr[rr] = *(const float4*)(Xb + rr * 68 + c4 * 4);
#pragma unroll
                for (int j = 0; j < 4; ++j) {
                    float4 g = G4[(c4 * 4 + j) * 24 + gcol];
#pragma unroll
                    for (int rr = 0; rr < 5; ++rr) {
                        float xv = (j == 0) ? xr[rr].x : (j == 1) ? xr[rr].y
                                 : (j == 2) ? xr[rr].z : xr[rr].w;
                        a0[rr] += xv * g.x; a1[rr] += xv * g.y;
                        a2[rr] += xv * g.z; a3[rr] += xv * g.w;
                    }
                }
            }
            const int bb0 = qk * 48 + kq_e * 16 + i4 * 4;
            const float b0 = bs[bb0], b1 = bs[bb0 + 1], b2 = bs[bb0 + 2], b3 = bs[bb0 + 3];
            // transposed store: E[i][v], row stride 28
            float* eb = (qk ? Kt : Qt) + t2 * 1344 + kq_e * 448 + (i4 * 4) * 28;
#pragma unroll
            for (int rr = 0; rr < 5; ++rr) {
                int row = rowg * 5 + rr;
                eb[row]      = a0[rr] + b0;
                eb[28 + row] = a1[rr] + b1;
                eb[56 + row] = a2[rr] + b2;
                eb[84 + row] = a3[rr] + b3;
            }
        }
        __syncthreads();

        // --- Score accumulation: S[k][4v][4w] += Q^T.K over i=16, 2 t's ---
        if (score_active) {
#pragma unroll
            for (int ti = 0; ti < 2; ++ti) {
                const float4* qv = (const float4*)(Qt + ti * 1344 + kq_s * 448 + vp_s * 4);
                const float4* kt = (const float4*)(Kt + ti * 1344 + kq_s * 448 + w4_s * 4);
#pragma unroll
                for (int i = 0; i < 16; ++i) {
                    float4 q  = qv[i * 7];
                    float4 kv = kt[i * 7];
                    acc[0][0] += q.x * kv.x; acc[0][1] += q.x * kv.y;
                    acc[0][2] += q.x * kv.z; acc[0][3] += q.x * kv.w;
                    acc[1][0] += q.y * kv.x; acc[1][1] += q.y * kv.y;
                    acc[1][2] += q.y * kv.z; acc[1][3] += q.y * kv.w;
                    acc[2][0] += q.z * kv.x; acc[2][1] += q.z * kv.y;
                    acc[2][2] += q.z * kv.z; acc[2][3] += q.z * kv.w;
                    acc[3][0] += q.w * kv.x; acc[3][1] += q.w * kv.y;
                    acc[3][2] += q.w * kv.z; acc[3][3] += q.w * kv.w;
                }
            }
        }
    }

    // --- write chunk partials (guards discard the pad-lane garbage) ---
    if (score_active) {
        float* base = g_Spart + ((chunk * 3 + kq_s) * 64 + n) * 625;
#pragma unroll
        for (int vi = 0; vi < 4; ++vi) {
            int v = vp_s * 4 + vi;
            if (v < 25) {
#pragma unroll
                for (int j = 0; j < 4; ++j) {
                    int w = w4_s * 4 + j;
                    if (w < 25) base[v * 25 + w] = acc[vi][j];
                }
            }
        }
    }
}

// ---------------------------------------------------------------------------
// Kernel 2: reduce chunk partials (deterministic order), softmax, add A.
// ---------------------------------------------------------------------------
__global__ __launch_bounds__(128) void softmax_kernel(const float* __restrict__ A)
{
    __shared__ float S[625];
    const int b = blockIdx.x;
    const int kq = b / 64, n = b % 64;
    const int tid = threadIdx.x;

    for (int e = tid; e < 625; e += 128) {
        float s = 0.f;
        int base = ((kq * 64) + n) * 625 + e;
#pragma unroll 6
        for (int ch = 0; ch < 30; ++ch) s += g_Spart[ch * 120000 + base];
        S[e] = s;
    }
    __syncthreads();

    if (tid < 25) {
        const int v = tid;
        float m = -1e30f;
#pragma unroll
        for (int w = 0; w < 25; ++w) {
            float z = S[v * 25 + w] * SCALE_D;
            m = fmaxf(m, z);
        }
        float p[25];
        float sum = 0.f;
#pragma unroll
        for (int w = 0; w < 25; ++w) {
            p[w] = expf(S[v * 25 + w] * SCALE_D - m);
            sum += p[w];
        }
        float inv = 1.f / sum;
        float* dst = g_Aad + ((kq * 64) + n) * 625 + v * 25;
        const float* Ab = A + kq * 625 + v * 25;
#pragma unroll
        for (int w = 0; w < 25; ++w) dst[w] = Ab[w] + p[w] * inv;
    }
}

// ---------------------------------------------------------------------------
// Kernel 3: main path. Grid (25 t-chunks of 12, 64 n), 256 threads.
// H = X*W (c4-vectorized), Y retiled 2w x 4f on 208 threads with float2 A +
// float4 H loads (A_adapt stored with padded row stride 28 for alignment).
// ---------------------------------------------------------------------------
__global__ __launch_bounds__(256) void main_kernel(
    const float* __restrict__ x, const float* __restrict__ W,
    const float* __restrict__ b, float* __restrict__ y)
{
    extern __shared__ float sm[];
    float* Ws    = sm;             // [64][192] = 12288
    float* Xs    = Ws + 12288;     // [25][68] padded = 1700
    float* Hs    = Xs + 1700;      // [25][192] = 4800
    float* ybias = Hs + 4800;      // [25][64]  = 1600
    float* As    = ybias + 1600;   // [3][25][28] padded = 2100
    float* csum  = As + 2100;      // [3][25]+pad = 77
    // total 22565 floats = 90260 B

    const int tid = threadIdx.x;
    const int n = blockIdx.y;
    const int tc = blockIdx.x;

    {   // load W (contiguous)
        const float4* src = (const float4*)W;
        float4* dst = (float4*)Ws;
        for (int e = tid; e < 3072; e += 256) dst[e] = src[e];
    }
    // load A_adapt for this n, repack to row stride 28
    for (int e = tid; e < 1875; e += 256) {
        int k = e / 625, rem = e % 625;
        int v = rem / 25, w = rem % 25;
        As[k * 700 + v * 28 + w] = g_Aad[(k * 64 + n) * 625 + rem];
    }
    __syncthreads();

    if (tid < 75) {
        int k = tid / 25, w = tid % 25;
        float s = 0.f;
#pragma unroll
        for (int v = 0; v < 25; ++v) s += As[k * 700 + v * 28 + w];
        csum[tid] = s;
    }
    __syncthreads();
    for (int e = tid; e < 1600; e += 256) {
        int w = e / 64, f = e % 64;
        ybias[e] = b[f] * csum[w] + b[64 + f] * csum[25 + w] + b[128 + f] * csum[50 + w];
    }

    const int col4 = tid % 48;      // H phase (tid < 240)
    const int rowg = tid / 48;
    const int wg = tid / 16;        // Y phase (tid < 208): w-pair 0..12
    const int f4 = tid % 16;        // f-group 0..15
    const int w0 = 2 * wg;
    const int w1 = 2 * wg + 1;

    for (int tt = 0; tt < 12; ++tt) {
        const int t = tc * 12 + tt;
        __syncthreads();
        {   // load X tile (400 float4), remap rows to stride 68
            const float4* src = (const float4*)(x + (n * 300 + t) * 1600);
            float4* dst = (float4*)Xs;
            for (int e = tid; e < 400; e += 256) {
                int row = e >> 4, col = e & 15;
                dst[row * 17 + col] = src[e];
            }
        }
        __syncthreads();

        // --- H = X * W : 25x192, 5 rows x float4 per thread, c4-vectorized ---
        if (tid < 240) {
            float a0[5], a1[5], a2[5], a3[5];
#pragma unroll
            for (int r = 0; r < 5; ++r) { a0[r] = a1[r] = a2[r] = a3[r] = 0.f; }
            const float* Xb = Xs + rowg * 340;
            const float4* W4 = (const float4*)Ws;
#pragma unroll 4
            for (int c4 = 0; c4 < 16; ++c4) {
                float4 xr[5];
#pragma unroll
                for (int r = 0; r < 5; ++r)
                    xr[r] = *(const float4*)(Xb + r * 68 + c4 * 4);
#pragma unroll
                for (int j = 0; j < 4; ++j) {
                    float4 wv = W4[(c4 * 4 + j) * 48 + col4];
#pragma unroll
                    for (int r = 0; r < 5; ++r) {
                        float xv = (j == 0) ? xr[r].x : (j == 1) ? xr[r].y
                                 : (j == 2) ? xr[r].z : xr[r].w;
                        a0[r] += xv * wv.x; a1[r] += xv * wv.y;
                        a2[r] += xv * wv.z; a3[r] += xv * wv.w;
                    }
                }
            }
            float4* H4 = (float4*)Hs;
#pragma unroll
            for (int r = 0; r < 5; ++r)
                H4[(rowg * 5 + r) * 48 + col4] = make_float4(a0[r], a1[r], a2[r], a3[r]);
        }
        __syncthreads();

        // --- Y: 2w x 4f tiles, 208 threads. float4 H + float2 A per v. ---
        if (tid < 208) {
            const float4* H4 = (const float4*)Hs;
            const float4* yb4 = (const float4*)ybias;
            float4 s0 = yb4[w0 * 16 + f4];
            float4 s1 = (w1 < 25) ? yb4[w1 * 16 + f4] : make_float4(0.f, 0.f, 0.f, 0.f);
#pragma unroll
            for (int k = 0; k < 3; ++k) {
                const float* Ab = As + k * 700 + 2 * wg;
                const int hcol = k * 16 + f4;
#pragma unroll
                for (int v = 0; v < 25; ++v) {
                    float4 h = H4[v * 48 + hcol];
                    float2 a = *(const float2*)(Ab + v * 28);
                    s0.x += a.x * h.x; s0.y += a.x * h.y;
                    s0.z += a.x * h.z; s0.w += a.x * h.w;
                    s1.x += a.y * h.x; s1.y += a.y * h.y;
                    s1.z += a.y * h.z; s1.w += a.y * h.w;
                }
            }
            float4* yout = (float4*)(y + (n * 300 + t) * 1600);
            yout[w0 * 16 + f4] = s0;
            if (w1 < 25) yout[w1 * 16 + f4] = s1;
        }
    }
}

// ---------------------------------------------------------------------------
extern "C" void kernel_launch(void* const* d_in, const int* in_sizes, int n_in,
                              void* d_out, int out_size)
{
    const float* x  = (const float*)d_in[0];
    const float* A  = (const float*)d_in[1];
    const float* W  = (const float*)d_in[2];
    const float* b  = (const float*)d_in[3];
    const float* Wq = (const float*)d_in[4];
    const float* bq = (const float*)d_in[5];
    const float* Wk = (const float*)d_in[6];
    const float* bk = (const float*)d_in[7];
    float* y = (float*)d_out;

    const int score_smem = 15016 * 4;   // 60064 B
    const int main_smem  = 22565 * 4;   // 90260 B
    cudaFuncSetAttribute(score_kernel, cudaFuncAttributeMaxDynamicSharedMemorySize, score_smem);
    cudaFuncSetAttribute(main_kernel,  cudaFuncAttributeMaxDynamicSharedMemorySize, main_smem);

    score_kernel<<<dim3(30, 64), 256, score_smem>>>(x, Wq, bq, Wk, bk);
    softmax_kernel<<<192, 128>>>(A);
    main_kernel<<<dim3(25, 64), 256, main_smem>>>(x, W, b, y);
}